// round 4
// baseline (speedup 1.0000x reference)
#include <cuda_runtime.h>
#include <math.h>

#define G     1024
#define GM    (G - 1)
#define NA    262144
#define NC    8
#define DT_F  0.1f
#define DEC_F 0.99f
#define SANG  0.6f
#define SLEN  3.0f

// Scratch (static device globals; no allocation anywhere)
__device__ float g_box[G * G * NC];       // 3x3 box sum, transposed (G,G,C) 32 MB
__device__ float g_dpher[NA * NC];        // per-agent pheromone delta        8 MB
__device__ int   g_winner[G * G];         // last-writer agent index + 1      4 MB (zero-init)

__device__ __forceinline__ float tanh_ap(float x) {
    float y; asm("tanh.approx.f32 %0, %1;" : "=f"(y) : "f"(x)); return y;
}

// ---------------------------------------------------------------------------
// Pass 1 (fused): wrapped 3x3 box sum, (C,G,G) -> transposed (G,G,C).
// Tile 16(x) x 64(y) per block, smem tile with halo, loop over channels.
// ---------------------------------------------------------------------------
#define TX 16
#define TY 64
__global__ __launch_bounds__(256) void k_box(const float* __restrict__ lat) {
    __shared__ float s[TX + 2][TY + 4];
    int y0 = blockIdx.x * TY;
    int x0 = blockIdx.y * TX;
    int tid = threadIdx.x;
    int tx  = tid >> 4;                        // 0..15
    int qy  = (tid & 15) << 2;                 // 0,4,...,60

    float o[4][NC];
#pragma unroll 1
    for (int c = 0; c < NC; c++) {
        __syncthreads();                       // protect previous iteration's reads
        for (int l = tid; l < (TX + 2) * (TY + 2); l += 256) {
            int i = l / (TY + 2);
            int j = l - i * (TY + 2);
            int xx = (x0 + i - 1) & GM;
            int yy = (y0 + j - 1) & GM;
            s[i][j] = lat[(size_t)c * (G * G) + (size_t)xx * G + yy];
        }
        __syncthreads();
        float cs[6];
#pragma unroll
        for (int m = 0; m < 6; m++)
            cs[m] = s[tx][qy + m] + s[tx + 1][qy + m] + s[tx + 2][qy + m];
#pragma unroll
        for (int u = 0; u < 4; u++)
            o[u][c] = cs[u] + cs[u + 1] + cs[u + 2];
    }

#pragma unroll
    for (int u = 0; u < 4; u++) {
        float4* d = (float4*)(g_box + ((size_t)((x0 + tx) * G + y0 + qy + u)) * NC);
        d[0] = make_float4(o[u][0], o[u][1], o[u][2], o[u][3]);
        d[1] = make_float4(o[u][4], o[u][5], o[u][6], o[u][7]);
    }
}

// ---------------------------------------------------------------------------
// Pass 2: per-agent sense + MLP (scalar fmaf + tanh.approx) + deposit claim.
// ---------------------------------------------------------------------------
__global__ __launch_bounds__(256) void k_agent(
    const float* __restrict__ pos, const float* __restrict__ vel,
    const float* __restrict__ W1,  const float* __restrict__ b1,
    const float* __restrict__ W2,  const float* __restrict__ b2,
    float* __restrict__ out)
{
    __shared__ __align__(16) float sW1[24 * 64];
    __shared__ __align__(16) float sB1[64];
    __shared__ __align__(16) float sW2[64 * 12];   // 10 outputs padded to 12
    __shared__ __align__(16) float sB2[12];

    int tid = threadIdx.x;
    for (int i = tid; i < 24 * 64; i += 256) sW1[i] = __ldg(W1 + i);
    if (tid < 64) sB1[tid] = __ldg(b1 + tid);
    for (int i = tid; i < 64 * 12; i += 256) {
        int k = i / 12, m = i - k * 12;
        sW2[i] = (m < 10) ? __ldg(W2 + k * 10 + m) : 0.0f;
    }
    if (tid < 12) sB2[tid] = (tid < 10) ? __ldg(b2 + tid) : 0.0f;
    __syncthreads();

    int a = blockIdx.x * 256 + tid;
    float px = pos[a],      py = pos[NA + a];
    float vx = vel[a],      vy = vel[NA + a];
    float th = atan2f(vy, vx);

    float x[24];
    const float offs[3] = {0.0f, SANG, -SANG};
#pragma unroll
    for (int s = 0; s < 3; s++) {
        float sa, ca;
        sincosf(th + offs[s], &sa, &ca);
        int ix = ((int)rintf(px + SLEN * ca)) & GM;   // == Python % (G pow2)
        int iy = ((int)rintf(py + SLEN * sa)) & GM;
        const float4* bp = (const float4*)(g_box + ((size_t)(ix * G + iy)) * NC);
        float4 u = bp[0], v = bp[1];
        x[s * 8 + 0] = u.x; x[s * 8 + 1] = u.y; x[s * 8 + 2] = u.z; x[s * 8 + 3] = u.w;
        x[s * 8 + 4] = v.x; x[s * 8 + 5] = v.y; x[s * 8 + 6] = v.z; x[s * 8 + 7] = v.w;
    }

    // Layer 1: h = tanh(x @ W1 + b1); fully unrolled, float4 across hidden dim
    float h[64];
#pragma unroll
    for (int jq = 0; jq < 16; jq++) {
        float4 acc = *(const float4*)&sB1[jq * 4];
#pragma unroll
        for (int k = 0; k < 24; k++) {
            float4 w = *(const float4*)&sW1[k * 64 + jq * 4];
            acc.x = fmaf(x[k], w.x, acc.x);
            acc.y = fmaf(x[k], w.y, acc.y);
            acc.z = fmaf(x[k], w.z, acc.z);
            acc.w = fmaf(x[k], w.w, acc.w);
        }
        h[jq * 4 + 0] = tanh_ap(acc.x);
        h[jq * 4 + 1] = tanh_ap(acc.y);
        h[jq * 4 + 2] = tanh_ap(acc.z);
        h[jq * 4 + 3] = tanh_ap(acc.w);
    }

    // Layer 2: o = h @ W2 + b2 (10 real outputs, padded to 12)
    float4 aA = *(const float4*)&sB2[0];
    float4 aB = *(const float4*)&sB2[4];
    float4 aC = *(const float4*)&sB2[8];
#pragma unroll
    for (int k = 0; k < 64; k++) {
        float hk = h[k];
        const float4* wr = (const float4*)&sW2[k * 12];
        float4 w0 = wr[0], w1 = wr[1], w2 = wr[2];
        aA.x = fmaf(hk, w0.x, aA.x); aA.y = fmaf(hk, w0.y, aA.y);
        aA.z = fmaf(hk, w0.z, aA.z); aA.w = fmaf(hk, w0.w, aA.w);
        aB.x = fmaf(hk, w1.x, aB.x); aB.y = fmaf(hk, w1.y, aB.y);
        aB.z = fmaf(hk, w1.z, aB.z); aB.w = fmaf(hk, w1.w, aB.w);
        aC.x = fmaf(hk, w2.x, aC.x); aC.y = fmaf(hk, w2.y, aC.y);
    }

    float nvx = aA.x, nvy = aA.y;
    float npx = px + nvx * DT_F;
    float npy = py + nvy * DT_F;
    npx -= floorf(npx * (1.0f / G)) * (float)G;   // jnp.mod fp32, G pow2 exact
    npy -= floorf(npy * (1.0f / G)) * (float)G;

    out[a]          = npx;
    out[NA + a]     = npy;
    out[2 * NA + a] = nvx;
    out[3 * NA + a] = nvy;

    float4* dp = (float4*)(g_dpher + (size_t)a * NC);
    dp[0] = make_float4(aA.z, aA.w, aB.x, aB.y);
    dp[1] = make_float4(aB.z, aB.w, aC.x, aC.y);

    int pix = (int)rintf(px) & GM;
    int piy = (int)rintf(py) & GM;
    atomicMax(&g_winner[pix * G + piy], a + 1);   // "last update wins"
}

// ---------------------------------------------------------------------------
// Pass 3: resolve deposits + decay; 4 cells x 8 channels per thread (float4).
// Resets g_winner so graph replays are identical.
// ---------------------------------------------------------------------------
__global__ void k_update(const float* __restrict__ lat, float* __restrict__ out) {
    int t = blockIdx.x * blockDim.x + threadIdx.x;     // G*G/4 threads
    int4 w4 = ((const int4*)g_winner)[t];
    int wl[4] = {w4.x, w4.y, w4.z, w4.w};
    if (wl[0] | wl[1] | wl[2] | wl[3])
        ((int4*)g_winner)[t] = make_int4(0, 0, 0, 0);

    float dp[4][NC];
#pragma unroll
    for (int u = 0; u < 4; u++) {
        if (wl[u]) {
            const float4* q = (const float4*)(g_dpher + (size_t)(wl[u] - 1) * NC);
            float4 a = q[0], b = q[1];
            dp[u][0] = a.x; dp[u][1] = a.y; dp[u][2] = a.z; dp[u][3] = a.w;
            dp[u][4] = b.x; dp[u][5] = b.y; dp[u][6] = b.z; dp[u][7] = b.w;
        }
    }

    const float4* l4 = (const float4*)lat;
    float4*       o4 = (float4*)(out + 4 * NA);
#pragma unroll
    for (int c = 0; c < NC; c++) {
        float4 v = l4[(size_t)c * (G * G / 4) + t];
        float* vv = (float*)&v;
#pragma unroll
        for (int u = 0; u < 4; u++)
            if (wl[u]) vv[u] = fmaxf(vv[u] + DT_F * dp[u][c], 0.0f);
        v.x *= DEC_F; v.y *= DEC_F; v.z *= DEC_F; v.w *= DEC_F;
        o4[(size_t)c * (G * G / 4) + t] = v;
    }
}

// ---------------------------------------------------------------------------
extern "C" void kernel_launch(void* const* d_in, const int* in_sizes, int n_in,
                              void* d_out, int out_size) {
    const float* pos = (const float*)d_in[0];
    const float* vel = (const float*)d_in[1];
    const float* lat = (const float*)d_in[2];
    const float* W1  = (const float*)d_in[3];
    const float* b1  = (const float*)d_in[4];
    const float* W2  = (const float*)d_in[5];
    const float* b2  = (const float*)d_in[6];
    float* out = (float*)d_out;

    dim3 bgrid(G / TY, G / TX);
    k_box   <<<bgrid, 256>>>(lat);
    k_agent <<<NA / 256, 256>>>(pos, vel, W1, b1, W2, b2, out);
    k_update<<<(G * G / 4) / 256, 256>>>(lat, out);
}

// round 5
// speedup vs baseline: 1.0179x; 1.0179x over previous
#include <cuda_runtime.h>
#include <math.h>

#define G     1024
#define GM    (G - 1)
#define NA    262144
#define NC    8
#define DT_F  0.1f
#define DEC_F 0.99f
#define SANG  0.6f
#define SLEN  3.0f

// Scratch (static device globals; no allocation anywhere)
__device__ float g_box[G * G * NC];       // 3x3 box sum, transposed (G,G,C) 32 MB
__device__ float g_dpher[NA * NC];        // per-agent pheromone delta        8 MB
__device__ int   g_winner[G * G];         // last-writer agent index + 1      4 MB (zero-init)

// ---- packed f32x2 helpers (PTX ISA sm_100+) --------------------------------
typedef unsigned long long u64;
__device__ __forceinline__ u64 pack2(float a, float b) {
    u64 r; asm("mov.b64 %0, {%1, %2};" : "=l"(r) : "f"(a), "f"(b)); return r;
}
__device__ __forceinline__ void unpack2(u64 v, float& a, float& b) {
    asm("mov.b64 {%0, %1}, %2;" : "=f"(a), "=f"(b) : "l"(v));
}
__device__ __forceinline__ void fma2(u64& d, u64 a, u64 b) {
    asm("fma.rn.f32x2 %0, %1, %2, %0;" : "+l"(d) : "l"(a), "l"(b));
}
__device__ __forceinline__ float tanh_ap(float x) {
    float y; asm("tanh.approx.f32 %0, %1;" : "=f"(y) : "f"(x)); return y;
}

// ---------------------------------------------------------------------------
// Pass 1: wrapped 3x3 box sum, (C,G,G) -> (G,G,C), direct streaming (no smem,
// no syncs). Thread t handles cells (x, y0..y0+3), all channels. L2 provides
// the 3x row reuse; DRAM traffic = 32 MB read + 32 MB write.
// ---------------------------------------------------------------------------
__global__ __launch_bounds__(256) void k_box(const float* __restrict__ lat) {
    int t  = blockIdx.x * 256 + threadIdx.x;   // G*G/4 threads
    int y0 = (t & 255) << 2;                   // 0,4,...,1020
    int x  = t >> 8;
    int xm = (x + GM) & GM;
    int xp = (x + 1) & GM;
    int ylo = (y0 + GM) & GM;                  // y0-1 wrapped
    int yhi = (y0 + 4) & GM;                   // y0+4 wrapped

    float o[4][NC];
#pragma unroll 1
    for (int c = 0; c < NC; c++) {
        const float* base = lat + (size_t)c * (G * G);
        float cs[6] = {0, 0, 0, 0, 0, 0};
        const int rows[3] = {xm, x, xp};
#pragma unroll
        for (int r = 0; r < 3; r++) {
            const float* rp = base + (size_t)rows[r] * G;
            float4 m = __ldg((const float4*)(rp + y0));
            cs[0] += __ldg(rp + ylo);
            cs[1] += m.x; cs[2] += m.y; cs[3] += m.z; cs[4] += m.w;
            cs[5] += __ldg(rp + yhi);
        }
#pragma unroll
        for (int u = 0; u < 4; u++)
            o[u][c] = cs[u] + cs[u + 1] + cs[u + 2];
    }

#pragma unroll
    for (int u = 0; u < 4; u++) {
        float4* d = (float4*)(g_box + ((size_t)(x * G + y0 + u)) * NC);
        d[0] = make_float4(o[u][0], o[u][1], o[u][2], o[u][3]);
        d[1] = make_float4(o[u][4], o[u][5], o[u][6], o[u][7]);
    }
}

// ---------------------------------------------------------------------------
// Pass 2: per-agent sense + MLP (packed f32x2 + tanh.approx) + deposit claim.
// ---------------------------------------------------------------------------
__global__ __launch_bounds__(128) void k_agent(
    const float* __restrict__ pos, const float* __restrict__ vel,
    const float* __restrict__ W1,  const float* __restrict__ b1,
    const float* __restrict__ W2,  const float* __restrict__ b2,
    float* __restrict__ out)
{
    __shared__ __align__(16) float sW1[24 * 64];
    __shared__ __align__(16) float sB1[64];
    __shared__ __align__(16) float sW2[64 * 12];   // 10 outputs padded to 12
    __shared__ __align__(16) float sB2[12];

    int tid = threadIdx.x;
    for (int i = tid; i < 24 * 64; i += 128) sW1[i] = __ldg(W1 + i);
    if (tid < 64) sB1[tid] = __ldg(b1 + tid);
    for (int i = tid; i < 64 * 12; i += 128) {
        int k = i / 12, m = i - k * 12;
        sW2[i] = (m < 10) ? __ldg(W2 + k * 10 + m) : 0.0f;
    }
    if (tid < 12) sB2[tid] = (tid < 10) ? __ldg(b2 + tid) : 0.0f;
    __syncthreads();

    int a = blockIdx.x * 128 + tid;
    float px = pos[a],      py = pos[NA + a];
    float vx = vel[a],      vy = vel[NA + a];
    float th = atan2f(vy, vx);

    u64 xpk[24];                               // x[k] duplicated into both lanes
    const float offs[3] = {0.0f, SANG, -SANG};
#pragma unroll
    for (int s = 0; s < 3; s++) {
        float sa, ca;
        sincosf(th + offs[s], &sa, &ca);
        int ix = ((int)rintf(px + SLEN * ca)) & GM;   // == Python % (G pow2)
        int iy = ((int)rintf(py + SLEN * sa)) & GM;
        const float4* bp = (const float4*)(g_box + ((size_t)(ix * G + iy)) * NC);
        float4 u = bp[0], v = bp[1];
        xpk[s * 8 + 0] = pack2(u.x, u.x); xpk[s * 8 + 1] = pack2(u.y, u.y);
        xpk[s * 8 + 2] = pack2(u.z, u.z); xpk[s * 8 + 3] = pack2(u.w, u.w);
        xpk[s * 8 + 4] = pack2(v.x, v.x); xpk[s * 8 + 5] = pack2(v.y, v.y);
        xpk[s * 8 + 6] = pack2(v.z, v.z); xpk[s * 8 + 7] = pack2(v.w, v.w);
    }

    // Layer 1: 32 packed accumulators (hidden pairs), fma.rn.f32x2
    u64 acc[32];
#pragma unroll
    for (int q = 0; q < 16; q++) {
        ulonglong2 bq = ((const ulonglong2*)sB1)[q];
        acc[2 * q] = bq.x; acc[2 * q + 1] = bq.y;
    }
#pragma unroll
    for (int k = 0; k < 24; k++) {
        u64 xk = xpk[k];
        const ulonglong2* wr = (const ulonglong2*)&sW1[k * 64];
#pragma unroll
        for (int q = 0; q < 16; q++) {
            ulonglong2 w = wr[q];
            fma2(acc[2 * q],     xk, w.x);
            fma2(acc[2 * q + 1], xk, w.y);
        }
    }
    float h[64];
#pragma unroll
    for (int j = 0; j < 32; j++) {
        float a0, a1;
        unpack2(acc[j], a0, a1);
        h[2 * j]     = tanh_ap(a0);
        h[2 * j + 1] = tanh_ap(a1);
    }

    // Layer 2: 6 packed accumulators over 12 (padded) outputs
    u64 oc[6];
    {
        ulonglong2 q0 = ((const ulonglong2*)sB2)[0];
        ulonglong2 q1 = ((const ulonglong2*)sB2)[1];
        ulonglong2 q2 = ((const ulonglong2*)sB2)[2];
        oc[0] = q0.x; oc[1] = q0.y; oc[2] = q1.x; oc[3] = q1.y; oc[4] = q2.x; oc[5] = q2.y;
    }
#pragma unroll
    for (int k = 0; k < 64; k++) {
        u64 hk = pack2(h[k], h[k]);
        const ulonglong2* wr = (const ulonglong2*)&sW2[k * 12];
        ulonglong2 w0 = wr[0], w1 = wr[1], w2 = wr[2];
        fma2(oc[0], hk, w0.x); fma2(oc[1], hk, w0.y);
        fma2(oc[2], hk, w1.x); fma2(oc[3], hk, w1.y);
        fma2(oc[4], hk, w2.x); fma2(oc[5], hk, w2.y);
    }

    float nvx, nvy, d0, d1, d2, d3, d4, d5, d6, d7;
    unpack2(oc[0], nvx, nvy);
    unpack2(oc[1], d0, d1);
    unpack2(oc[2], d2, d3);
    unpack2(oc[3], d4, d5);
    unpack2(oc[4], d6, d7);

    float npx = px + nvx * DT_F;
    float npy = py + nvy * DT_F;
    npx -= floorf(npx * (1.0f / G)) * (float)G;   // jnp.mod fp32, G pow2 exact
    npy -= floorf(npy * (1.0f / G)) * (float)G;

    out[a]          = npx;
    out[NA + a]     = npy;
    out[2 * NA + a] = nvx;
    out[3 * NA + a] = nvy;

    float4* dp = (float4*)(g_dpher + (size_t)a * NC);
    dp[0] = make_float4(d0, d1, d2, d3);
    dp[1] = make_float4(d4, d5, d6, d7);

    int pix = (int)rintf(px) & GM;
    int piy = (int)rintf(py) & GM;
    atomicMax(&g_winner[pix * G + piy], a + 1);   // "last update wins"
}

// ---------------------------------------------------------------------------
// Pass 3: resolve deposits + decay; 4 cells x 8 channels per thread (float4).
// Resets g_winner so graph replays are identical.
// ---------------------------------------------------------------------------
__global__ void k_update(const float* __restrict__ lat, float* __restrict__ out) {
    int t = blockIdx.x * blockDim.x + threadIdx.x;     // G*G/4 threads
    int4 w4 = ((const int4*)g_winner)[t];
    int wl[4] = {w4.x, w4.y, w4.z, w4.w};
    if (wl[0] | wl[1] | wl[2] | wl[3])
        ((int4*)g_winner)[t] = make_int4(0, 0, 0, 0);

    float dp[4][NC];
#pragma unroll
    for (int u = 0; u < 4; u++) {
        if (wl[u]) {
            const float4* q = (const float4*)(g_dpher + (size_t)(wl[u] - 1) * NC);
            float4 a = q[0], b = q[1];
            dp[u][0] = a.x; dp[u][1] = a.y; dp[u][2] = a.z; dp[u][3] = a.w;
            dp[u][4] = b.x; dp[u][5] = b.y; dp[u][6] = b.z; dp[u][7] = b.w;
        }
    }

    const float4* l4 = (const float4*)lat;
    float4*       o4 = (float4*)(out + 4 * NA);
#pragma unroll
    for (int c = 0; c < NC; c++) {
        float4 v = l4[(size_t)c * (G * G / 4) + t];
        float* vv = (float*)&v;
#pragma unroll
        for (int u = 0; u < 4; u++)
            if (wl[u]) vv[u] = fmaxf(vv[u] + DT_F * dp[u][c], 0.0f);
        v.x *= DEC_F; v.y *= DEC_F; v.z *= DEC_F; v.w *= DEC_F;
        o4[(size_t)c * (G * G / 4) + t] = v;
    }
}

// ---------------------------------------------------------------------------
extern "C" void kernel_launch(void* const* d_in, const int* in_sizes, int n_in,
                              void* d_out, int out_size) {
    const float* pos = (const float*)d_in[0];
    const float* vel = (const float*)d_in[1];
    const float* lat = (const float*)d_in[2];
    const float* W1  = (const float*)d_in[3];
    const float* b1  = (const float*)d_in[4];
    const float* W2  = (const float*)d_in[5];
    const float* b2  = (const float*)d_in[6];
    float* out = (float*)d_out;

    k_box   <<<(G * G / 4) / 256, 256>>>(lat);
    k_agent <<<NA / 128, 128>>>(pos, vel, W1, b1, W2, b2, out);
    k_update<<<(G * G / 4) / 256, 256>>>(lat, out);
}

// round 6
// speedup vs baseline: 1.3088x; 1.2857x over previous
#include <cuda_runtime.h>
#include <math.h>

#define G     1024
#define GM    (G - 1)
#define NA    262144
#define NC    8
#define DT_F  0.1f
#define DEC_F 0.99f
#define SANG  0.6f
#define SLEN  3.0f

// Scratch (static device globals; no allocation anywhere)
__device__ float g_tmp1[NC * G * G];      // horizontal 3-sum, (C,G,G)       32 MB
__device__ float g_box[G * G * NC];       // 3x3 box sum, transposed (G,G,C) 32 MB
__device__ float g_dpher[NA * NC];        // per-agent pheromone delta        8 MB
__device__ int   g_winner[G * G];         // last-writer agent index + 1      4 MB (zero-init)

__device__ __forceinline__ float tanh_ap(float x) {
    float y; asm("tanh.approx.f32 %0, %1;" : "=f"(y) : "f"(x)); return y;
}

// ---------------------------------------------------------------------------
// Pass 1a: horizontal wrapped 3-sum along y.  tmp1[c][x][y] = L[y-1]+L[y]+L[y+1]
// ---------------------------------------------------------------------------
__global__ void k_hsum(const float* __restrict__ lat) {
    int t   = blockIdx.x * blockDim.x + threadIdx.x;   // C*G*G/4 threads
    int y0  = (t & 255) << 2;
    int row = t >> 8;                                  // c*G + x
    const float* r = lat + (size_t)row * G;
    float4 m = *(const float4*)(r + y0);
    float lm = __ldg(r + ((y0 + GM) & GM));
    float rp = __ldg(r + ((y0 + 4) & GM));
    float4 o;
    o.x = lm  + m.x + m.y;
    o.y = m.x + m.y + m.z;
    o.z = m.y + m.z + m.w;
    o.w = m.z + m.w + rp;
    *(float4*)(g_tmp1 + (size_t)row * G + y0) = o;
}

// ---------------------------------------------------------------------------
// Pass 1b: vertical wrapped 3-sum along x + transpose to (x,y,c).
// ---------------------------------------------------------------------------
__global__ void k_vsum() {
    int t  = blockIdx.x * blockDim.x + threadIdx.x;    // G*G threads
    int y  = t & GM;
    int x  = t >> 10;
    int xm = (x + GM) & GM;
    int xp = (x + 1) & GM;
    float o[NC];
#pragma unroll
    for (int c = 0; c < NC; c++) {
        const float* p = g_tmp1 + (size_t)c * (G * G);
        o[c] = p[xm * G + y] + p[x * G + y] + p[xp * G + y];
    }
    float4* dst = (float4*)(g_box + (size_t)t * NC);
    dst[0] = make_float4(o[0], o[1], o[2], o[3]);
    dst[1] = make_float4(o[4], o[5], o[6], o[7]);
}

// ---------------------------------------------------------------------------
// Pass 2: per-agent sense + MLP + outputs. 2 agents per thread (shared weight
// loads), layer-2 fused into the layer-1 hidden loop (h never stored).
// ---------------------------------------------------------------------------
__device__ __forceinline__ void sense24(float px, float py, float vx, float vy,
                                        float* __restrict__ x) {
    const float CA = 0.8253356149096783f;   // cos(0.6)
    const float SA = 0.5646424733950354f;   // sin(0.6)
    float rinv = rsqrtf(vx * vx + vy * vy);
    float c0 = vx * rinv, s0 = vy * rinv;
    float cd[3], sd[3];
    cd[0] = c0;                 sd[0] = s0;                 // front
    cd[1] = c0 * CA - s0 * SA;  sd[1] = s0 * CA + c0 * SA;  // +SENSOR_ANGLE
    cd[2] = c0 * CA + s0 * SA;  sd[2] = s0 * CA - c0 * SA;  // -SENSOR_ANGLE
#pragma unroll
    for (int s = 0; s < 3; s++) {
        int ix = ((int)rintf(px + SLEN * cd[s])) & GM;
        int iy = ((int)rintf(py + SLEN * sd[s])) & GM;
        const float4* bp = (const float4*)(g_box + ((size_t)(ix * G + iy)) * NC);
        float4 u = bp[0], v = bp[1];
        x[s * 8 + 0] = u.x; x[s * 8 + 1] = u.y; x[s * 8 + 2] = u.z; x[s * 8 + 3] = u.w;
        x[s * 8 + 4] = v.x; x[s * 8 + 5] = v.y; x[s * 8 + 6] = v.z; x[s * 8 + 7] = v.w;
    }
}

__global__ __launch_bounds__(256) void k_agent(
    const float* __restrict__ pos, const float* __restrict__ vel,
    const float* __restrict__ W1,  const float* __restrict__ b1,
    const float* __restrict__ W2,  const float* __restrict__ b2,
    float* __restrict__ out)
{
    __shared__ __align__(16) float sW1[24 * 64];
    __shared__ __align__(16) float sB1[64];
    __shared__ __align__(16) float sW2[64 * 12];   // rows of 10 padded to 12
    __shared__ __align__(16) float sB2[12];

    int tid = threadIdx.x;
    for (int i = tid; i < 24 * 64; i += 256) sW1[i] = __ldg(W1 + i);
    if (tid < 64) sB1[tid] = __ldg(b1 + tid);
    for (int i = tid; i < 64 * 12; i += 256) {
        int k = i / 12, m = i - k * 12;
        sW2[i] = (m < 10) ? __ldg(W2 + k * 10 + m) : 0.0f;
    }
    if (tid < 12) sB2[tid] = (tid < 10) ? __ldg(b2 + tid) : 0.0f;
    __syncthreads();

    int aA = blockIdx.x * 512 + tid;     // two agents per thread
    int aB = aA + 256;

    float pxA = pos[aA], pyA = pos[NA + aA];
    float vxA = vel[aA], vyA = vel[NA + aA];
    float pxB = pos[aB], pyB = pos[NA + aB];
    float vxB = vel[aB], vyB = vel[NA + aB];

    float xA[24], xB[24];
    sense24(pxA, pyA, vxA, vyA, xA);
    sense24(pxB, pyB, vxB, vyB, xB);

    float ocA[10], ocB[10];
#pragma unroll
    for (int m = 0; m < 10; m++) { ocA[m] = sB2[m]; ocB[m] = sB2[m]; }

    // hidden loop: 4 hidden units per iteration; layer2 fused
#pragma unroll
    for (int jq = 0; jq < 16; jq++) {
        float4 b4 = *(const float4*)&sB1[jq * 4];
        float4 aAcc = b4, bAcc = b4;
#pragma unroll
        for (int k = 0; k < 24; k++) {
            float4 w = *(const float4*)&sW1[k * 64 + jq * 4];
            aAcc.x = fmaf(xA[k], w.x, aAcc.x); aAcc.y = fmaf(xA[k], w.y, aAcc.y);
            aAcc.z = fmaf(xA[k], w.z, aAcc.z); aAcc.w = fmaf(xA[k], w.w, aAcc.w);
            bAcc.x = fmaf(xB[k], w.x, bAcc.x); bAcc.y = fmaf(xB[k], w.y, bAcc.y);
            bAcc.z = fmaf(xB[k], w.z, bAcc.z); bAcc.w = fmaf(xB[k], w.w, bAcc.w);
        }
        float hA[4], hB[4];
        hA[0] = tanh_ap(aAcc.x); hA[1] = tanh_ap(aAcc.y);
        hA[2] = tanh_ap(aAcc.z); hA[3] = tanh_ap(aAcc.w);
        hB[0] = tanh_ap(bAcc.x); hB[1] = tanh_ap(bAcc.y);
        hB[2] = tanh_ap(bAcc.z); hB[3] = tanh_ap(bAcc.w);
#pragma unroll
        for (int u = 0; u < 4; u++) {
            int j = jq * 4 + u;
            const float4* wr = (const float4*)&sW2[j * 12];
            float4 w0 = wr[0], w1 = wr[1], w2 = wr[2];
            float ha = hA[u], hb = hB[u];
            ocA[0] = fmaf(ha, w0.x, ocA[0]); ocB[0] = fmaf(hb, w0.x, ocB[0]);
            ocA[1] = fmaf(ha, w0.y, ocA[1]); ocB[1] = fmaf(hb, w0.y, ocB[1]);
            ocA[2] = fmaf(ha, w0.z, ocA[2]); ocB[2] = fmaf(hb, w0.z, ocB[2]);
            ocA[3] = fmaf(ha, w0.w, ocA[3]); ocB[3] = fmaf(hb, w0.w, ocB[3]);
            ocA[4] = fmaf(ha, w1.x, ocA[4]); ocB[4] = fmaf(hb, w1.x, ocB[4]);
            ocA[5] = fmaf(ha, w1.y, ocA[5]); ocB[5] = fmaf(hb, w1.y, ocB[5]);
            ocA[6] = fmaf(ha, w1.z, ocA[6]); ocB[6] = fmaf(hb, w1.z, ocB[6]);
            ocA[7] = fmaf(ha, w1.w, ocA[7]); ocB[7] = fmaf(hb, w1.w, ocB[7]);
            ocA[8] = fmaf(ha, w2.x, ocA[8]); ocB[8] = fmaf(hb, w2.x, ocB[8]);
            ocA[9] = fmaf(ha, w2.y, ocA[9]); ocB[9] = fmaf(hb, w2.y, ocB[9]);
        }
    }

    // ---- epilogue per agent ----
    {
        float npx = pxA + ocA[0] * DT_F, npy = pyA + ocA[1] * DT_F;
        npx -= floorf(npx * (1.0f / G)) * (float)G;
        npy -= floorf(npy * (1.0f / G)) * (float)G;
        out[aA] = npx; out[NA + aA] = npy;
        out[2 * NA + aA] = ocA[0]; out[3 * NA + aA] = ocA[1];
        float4* dp = (float4*)(g_dpher + (size_t)aA * NC);
        dp[0] = make_float4(ocA[2], ocA[3], ocA[4], ocA[5]);
        dp[1] = make_float4(ocA[6], ocA[7], ocA[8], ocA[9]);
        int pix = (int)rintf(pxA) & GM, piy = (int)rintf(pyA) & GM;
        atomicMax(&g_winner[pix * G + piy], aA + 1);
    }
    {
        float npx = pxB + ocB[0] * DT_F, npy = pyB + ocB[1] * DT_F;
        npx -= floorf(npx * (1.0f / G)) * (float)G;
        npy -= floorf(npy * (1.0f / G)) * (float)G;
        out[aB] = npx; out[NA + aB] = npy;
        out[2 * NA + aB] = ocB[0]; out[3 * NA + aB] = ocB[1];
        float4* dp = (float4*)(g_dpher + (size_t)aB * NC);
        dp[0] = make_float4(ocB[2], ocB[3], ocB[4], ocB[5]);
        dp[1] = make_float4(ocB[6], ocB[7], ocB[8], ocB[9]);
        int pix = (int)rintf(pxB) & GM, piy = (int)rintf(pyB) & GM;
        atomicMax(&g_winner[pix * G + piy], aB + 1);
    }
}

// ---------------------------------------------------------------------------
// Pass 3: resolve deposits + decay; 4 cells x 8 channels per thread (float4).
// Resets g_winner so graph replays are identical.
// ---------------------------------------------------------------------------
__global__ void k_update(const float* __restrict__ lat, float* __restrict__ out) {
    int t = blockIdx.x * blockDim.x + threadIdx.x;     // G*G/4 threads
    int4 w4 = ((const int4*)g_winner)[t];
    int wl[4] = {w4.x, w4.y, w4.z, w4.w};
    if (wl[0] | wl[1] | wl[2] | wl[3])
        ((int4*)g_winner)[t] = make_int4(0, 0, 0, 0);

    float dp[4][NC];
#pragma unroll
    for (int u = 0; u < 4; u++) {
        if (wl[u]) {
            const float4* q = (const float4*)(g_dpher + (size_t)(wl[u] - 1) * NC);
            float4 a = q[0], b = q[1];
            dp[u][0] = a.x; dp[u][1] = a.y; dp[u][2] = a.z; dp[u][3] = a.w;
            dp[u][4] = b.x; dp[u][5] = b.y; dp[u][6] = b.z; dp[u][7] = b.w;
        }
    }

    const float4* l4 = (const float4*)lat;
    float4*       o4 = (float4*)(out + 4 * NA);
#pragma unroll
    for (int c = 0; c < NC; c++) {
        float4 v = l4[(size_t)c * (G * G / 4) + t];
        float* vv = (float*)&v;
#pragma unroll
        for (int u = 0; u < 4; u++)
            if (wl[u]) vv[u] = fmaxf(vv[u] + DT_F * dp[u][c], 0.0f);
        v.x *= DEC_F; v.y *= DEC_F; v.z *= DEC_F; v.w *= DEC_F;
        o4[(size_t)c * (G * G / 4) + t] = v;
    }
}

// ---------------------------------------------------------------------------
extern "C" void kernel_launch(void* const* d_in, const int* in_sizes, int n_in,
                              void* d_out, int out_size) {
    const float* pos = (const float*)d_in[0];
    const float* vel = (const float*)d_in[1];
    const float* lat = (const float*)d_in[2];
    const float* W1  = (const float*)d_in[3];
    const float* b1  = (const float*)d_in[4];
    const float* W2  = (const float*)d_in[5];
    const float* b2  = (const float*)d_in[6];
    float* out = (float*)d_out;

    k_hsum  <<<(NC * G * G / 4) / 256, 256>>>(lat);
    k_vsum  <<<(G * G) / 256, 256>>>();
    k_agent <<<NA / 512, 256>>>(pos, vel, W1, b1, W2, b2, out);
    k_update<<<(G * G / 4) / 256, 256>>>(lat, out);
}